// round 6
// baseline (speedup 1.0000x reference)
#include <cuda_runtime.h>
#include <cuda_fp16.h>
#include <math.h>
#include <stdint.h>

// Problem constants: B=64, N=1024, D=8, S=16 -> DS=128, K=1024
#define NN    1024
#define BB    64
#define DS    128
#define KDIM  1024
#define CHUNK 64                     // logical K per stage
#define NCH   (KDIM / CHUNK)         // 16

// smem stage geometry
#define A_ROWB   80                  // 64B compressed A row + 16B pad
#define B_ROWB   144                 // 128B B row + 16B pad
#define A_BYTES  (128 * A_ROWB)      // 10240
#define B_BYTES  (128 * B_ROWB)      // 18432
#define STG_SZ   (A_BYTES + B_BYTES) // 28672
#define C_STRIDE 129
#define SMEM_REQ (128 * C_STRIDE * 4 + 1024)   // 67072 (covers 2*STG_SZ)

__device__ __forceinline__ uint32_t smem_u32(const void* p) {
    uint32_t a;
    asm("{ .reg .u64 t; cvta.to.shared.u64 t, %1; cvt.u32.u64 %0, t; }" : "=r"(a) : "l"(p));
    return a;
}
__device__ __forceinline__ void cp16(uint32_t dst, const void* src) {
    asm volatile("cp.async.cg.shared.global [%0], [%1], 16;" :: "r"(dst), "l"(src) : "memory");
}
__device__ __forceinline__ void ldm_x4(uint32_t* r, uint32_t addr) {
    asm volatile("ldmatrix.sync.aligned.m8n8.x4.shared.b16 {%0,%1,%2,%3}, [%4];"
                 : "=r"(r[0]), "=r"(r[1]), "=r"(r[2]), "=r"(r[3]) : "r"(addr));
}
// 2:4 sparse HMMA: A compressed 16x16, B 32x8, metadata e, selector 0
__device__ __forceinline__ void mma_sp(float* c, const uint32_t* a, const uint32_t* b, uint32_t e) {
    asm volatile("mma.sp::ordered_metadata.sync.aligned.m16n8k32.row.col.f32.f16.f16.f32 "
                 "{%0,%1,%2,%3}, {%4,%5,%6,%7}, {%8,%9,%10,%11}, {%0,%1,%2,%3}, %12, 0x0;"
                 : "+f"(c[0]), "+f"(c[1]), "+f"(c[2]), "+f"(c[3])
                 : "r"(a[0]), "r"(a[1]), "r"(a[2]), "r"(a[3]),
                   "r"(b[0]), "r"(b[1]), "r"(b[2]), "r"(b[3]), "r"(e));
}

// ---------------- device scratch ------------------------------------------
__device__ __half   g_Ac[NN * (KDIM / 2)];     // compressed M fp16 [o][512]  (1 MB)
__device__ uint16_t g_m16[NN * (KDIM / 16)];   // 16-bit meta per (row, k16-grp)
__device__ uint32_t g_metaC[(NN / 2) * (KDIM / 16)];  // packed rows (r, r+8)
__device__ uint16_t g_dropidx[NN * 32];        // dropped i per row (cap 32)
__device__ int      g_dropcnt[NN];
__device__ __half   g_X[BB * DS * KDIM];       // xT fp16 [(b*128+ds)][i]    (16 MB)

// ---------------- prep 1: compress M to 2:4 sparse form --------------------
// One warp per o-row; lane handles one 4-wide i-group per iteration.
__global__ void compress_M(const float* __restrict__ M)
{
    const int row  = blockIdx.x * 8 + (threadIdx.x >> 5);
    const int lane = threadIdx.x & 31;
    int dropcnt = 0;

    for (int it = 0; it < 8; it++) {
        const int grp = it * 32 + lane;                  // 0..255
        const float4 v = ((const float4*)M)[row * 256 + grp];
        float vals[4] = {v.x, v.y, v.z, v.w};
        unsigned nz = (v.x != 0.f ? 1u : 0u) | (v.y != 0.f ? 2u : 0u)
                    | (v.z != 0.f ? 4u : 0u) | (v.w != 0.f ? 8u : 0u);

        // kept = first two nonzero positions, padded with lowest zero positions
        int i0 = -1, i1 = -1;
        for (int p = 0; p < 4; p++)
            if ((nz >> p) & 1) { if (i0 < 0) i0 = p; else if (i1 < 0) i1 = p; }
        for (int p = 0; p < 4; p++)
            if (!((nz >> p) & 1)) { if (i0 < 0) i0 = p; else if (i1 < 0) i1 = p; }
        const int a  = (i0 < i1) ? i0 : i1;
        const int b2 = (i0 < i1) ? i1 : i0;

        ((__half2*)g_Ac)[row * 256 + grp] = __floats2half2_rn(vals[a], vals[b2]);

        // 16-bit word per 4 groups (16 k): nibble j = group with (grp&3)==j
        unsigned part = ((unsigned)(a | (b2 << 2))) << (4 * (lane & 3));
        part |= __shfl_xor_sync(0xffffffffu, part, 1);
        part |= __shfl_xor_sync(0xffffffffu, part, 2);
        if ((lane & 3) == 0)
            g_m16[row * 64 + it * 8 + (lane >> 2)] = (uint16_t)part;

        // dropped entries (3rd/4th nonzeros) -> deterministic per-row list
        int c = __popc(nz) - 2; if (c < 0) c = 0;
        int sc = c;
#pragma unroll
        for (int o = 1; o < 32; o <<= 1) {
            int t = __shfl_up_sync(0xffffffffu, sc, o);
            if (lane >= o) sc += t;
        }
        const int base = dropcnt + (sc - c);
        if (c > 0) {
            int seen = 0, w = 0;
            for (int p = 0; p < 4; p++)
                if ((nz >> p) & 1) {
                    seen++;
                    if (seen > 2 && base + w < 32)
                        g_dropidx[row * 32 + base + (w++)] = (uint16_t)(grp * 4 + p);
                }
        }
        dropcnt += __shfl_sync(0xffffffffu, sc, 31);
    }
    if (lane == 0) g_dropcnt[row] = (dropcnt < 32) ? dropcnt : 32;
}

// ---------------- prep 1b: pack (row r lo | row r+8 hi) metadata words -----
// rhalf = (row>>4)*8 + (row&7), idx = k16-group. 32768 words total.
__global__ void combine_meta()
{
    const int t   = blockIdx.x * 256 + threadIdx.x;      // 0..32767
    const int r   = t >> 6, idx = t & 63;
    const int row = (r >> 3) * 16 + (r & 7);
    g_metaC[t] = (uint32_t)g_m16[row * 64 + idx]
               | ((uint32_t)g_m16[(row + 8) * 64 + idx] << 16);
}

// ---------------- prep 2: transpose x[b,i,ds] -> g_X[(b*128+ds), i] fp16 ---
__global__ void transpose_x(const float* __restrict__ x)
{
    __shared__ float t[64 * 33];
    const int b  = blockIdx.z;
    const int i0 = blockIdx.x * 64;
    const int d0 = blockIdx.y * 32;
    const int tid = threadIdx.x;

    const float* src = x + (size_t)b * (NN * DS) + (size_t)i0 * DS + d0;
#pragma unroll
    for (int idx = tid; idx < 64 * 32; idx += 256) {
        const int r = idx >> 5, c = idx & 31;
        t[r * 33 + c] = src[(size_t)r * DS + c];
    }
    __syncthreads();

    __half2* dst = (__half2*)g_X + (size_t)(b * DS + d0) * (KDIM / 2) + (i0 >> 1);
#pragma unroll
    for (int idx = tid; idx < 32 * 32; idx += 256) {
        const int dsr = idx >> 5, hc = idx & 31;
        dst[(size_t)dsr * (KDIM / 2) + hc] =
            __floats2half2_rn(t[(2 * hc) * 33 + dsr], t[(2 * hc + 1) * 33 + dsr]);
    }
}

// ---------------- sparse GEMM + fused dendrite/soma epilogue ---------------
// Grid (8, 64). Block 256 = 8 warps, warp tile m64 x n32 (2 m x 4 n).
__global__ void __launch_bounds__(256) gemm_neuron(
    const float* __restrict__ x,        // [B, N, 128] (for dropped-entry fixup)
    const float* __restrict__ w_syn,    // [N, 128]
    const float* __restrict__ b_dend,   // [N, 8]
    const float* __restrict__ w_dend,   // [N, 8]
    const float* __restrict__ b_soma,   // [N]
    float* __restrict__ out)            // [B, N]
{
    extern __shared__ char smem[];
    const uint32_t sb = smem_u32(smem);
    const int tid  = threadIdx.x;
    const int wid  = tid >> 5, lane = tid & 31;
    const int wm   = wid & 1;
    const int wn   = wid >> 1;
    const int o0   = blockIdx.x * 128;
    const int b    = blockIdx.y;

    // ldmatrix lane bases
    uint32_t offA[4], offB[4];
#pragma unroll
    for (int mt = 0; mt < 4; mt++)   // compressed A: 16 rows x 32B per kb
        offA[mt] = (uint32_t)(wm * 64 + mt * 16 + (lane & 7) + ((lane >> 3) & 1) * 8) * A_ROWB
                 + (lane >> 4) * 16;
#pragma unroll
    for (int nt = 0; nt < 4; nt++)   // B: 8 n-rows x 64B (k32) per kb
        offB[nt] = A_BYTES + (uint32_t)(wn * 32 + nt * 8 + (lane & 7)) * B_ROWB
                 + ((lane >> 3) & 3) * 16;

    float acc[4][4][4];
#pragma unroll
    for (int mt = 0; mt < 4; mt++)
#pragma unroll
        for (int nt = 0; nt < 4; nt++)
#pragma unroll
            for (int q = 0; q < 4; q++) acc[mt][nt][q] = 0.f;

    const __half* gA = g_Ac + (size_t)o0 * (KDIM / 2);
    const __half* gB = g_X + (size_t)(b * DS) * KDIM;

    // metadata: lanes ml = lane%4 < 2 supply e; T0 -> k0-15, T1 -> k16-31 of
    // rows (r, r+8) packed lo/hi. rhalf = (row>>4)*8 + (row&7).
    const int ml = lane & 3;
    const int rhbase = ((o0 >> 4) + wm * 4) * 8 + (lane >> 2);   // + mt*8

#define STAGE(c) do {                                                           \
    const uint32_t _base = sb + ((c) & 1) * STG_SZ;                             \
    _Pragma("unroll")                                                           \
    for (int it = 0; it < 2; it++) {                                            \
        const int g = tid + it * 256;                                           \
        const int row = g >> 2, col = g & 3;                                    \
        cp16(_base + row * A_ROWB + col * 16,                                   \
             gA + (size_t)row * (KDIM / 2) + (c) * 32 + col * 8);               \
    }                                                                           \
    _Pragma("unroll")                                                           \
    for (int it = 0; it < 4; it++) {                                            \
        const int g = tid + it * 256;                                           \
        const int row = g >> 3, col = g & 7;                                    \
        cp16(_base + A_BYTES + row * B_ROWB + col * 16,                         \
             gB + (size_t)row * KDIM + (c) * CHUNK + col * 8);                  \
    }                                                                           \
    asm volatile("cp.async.commit_group;" ::: "memory");                        \
} while (0)

    STAGE(0);
    for (int c = 0; c < NCH; c++) {
        if (c + 1 < NCH) {
            STAGE(c + 1);
            asm volatile("cp.async.wait_group 1;" ::: "memory");
        } else {
            asm volatile("cp.async.wait_group 0;" ::: "memory");
        }
        __syncthreads();

        const uint32_t base = sb + (c & 1) * STG_SZ;
#pragma unroll
        for (int kb = 0; kb < 2; kb++) {        // two k32 blocks per chunk
            uint32_t a[4][4], bf[4][4], e[4];
#pragma unroll
            for (int mt = 0; mt < 4; mt++) {
                ldm_x4(a[mt], base + offA[mt] + kb * 32);
                e[mt] = (ml < 2)
                      ? g_metaC[(rhbase + mt * 8) * 64 + c * 4 + kb * 2 + ml] : 0u;
            }
#pragma unroll
            for (int nt = 0; nt < 4; nt++) ldm_x4(bf[nt], base + offB[nt] + kb * 64);
#pragma unroll
            for (int mt = 0; mt < 4; mt++)
#pragma unroll
                for (int nt = 0; nt < 4; nt++)
                    mma_sp(acc[mt][nt], a[mt], bf[nt], e[mt]);
        }
        __syncthreads();
    }

    // ---- epilogue: frags -> C[128][129] fp32 ----
    float* C = (float*)smem;
#pragma unroll
    for (int mt = 0; mt < 4; mt++)
#pragma unroll
        for (int nt = 0; nt < 4; nt++) {
            const int r  = wm * 64 + mt * 16 + (lane >> 2);
            const int cc = wn * 32 + nt * 8 + (lane & 3) * 2;
            C[r * C_STRIDE + cc]           = acc[mt][nt][0];
            C[r * C_STRIDE + cc + 1]       = acc[mt][nt][1];
            C[(r + 8) * C_STRIDE + cc]     = acc[mt][nt][2];
            C[(r + 8) * C_STRIDE + cc + 1] = acc[mt][nt][3];
        }
    __syncthreads();

    // 2 threads per o-row: (row, half h of ds)
    const int row = tid & 127;
    const int h   = tid >> 7;
    const int o   = o0 + row;
    float td[4] = {0.f, 0.f, 0.f, 0.f};
    const float4* w4 = (const float4*)(w_syn + (size_t)o * 128 + h * 64);
#pragma unroll
    for (int j4 = 0; j4 < 16; j4++) {
        const float4 w = w4[j4];
        const int e0 = h * 64 + j4 * 4;
        td[j4 >> 2] += C[row * C_STRIDE + e0]     * w.x
                     + C[row * C_STRIDE + e0 + 1] * w.y
                     + C[row * C_STRIDE + e0 + 2] * w.z
                     + C[row * C_STRIDE + e0 + 3] * w.w;
    }
    // dropped-entry fixup: xm[o] missed +x[b,i,:] for each dropped i
    const int cnt = g_dropcnt[o];
    const float* xb = x + (size_t)b * (NN * DS);
    for (int j = 0; j < cnt; j++) {
        const int i = g_dropidx[o * 32 + j];
        const float4* xv = (const float4*)(xb + (size_t)i * DS + h * 64);
#pragma unroll
        for (int j4 = 0; j4 < 16; j4++) {
            const float4 w  = w4[j4];
            const float4 xx = xv[j4];
            td[j4 >> 2] += xx.x * w.x + xx.y * w.y + xx.z * w.z + xx.w * w.w;
        }
    }
    float sh = 0.f;
#pragma unroll
    for (int d = 0; d < 4; d++) {
        const int dd = h * 4 + d;
        sh += tanhf(td[d] + b_dend[o * 8 + dd]) * w_dend[o * 8 + dd];
    }
    float* spart = (float*)(smem + 128 * C_STRIDE * 4);
    spart[h * 128 + row] = sh;
    __syncthreads();
    if (tid < 128) {
        const float s = spart[tid] + spart[128 + tid] + b_soma[o0 + tid];
        out[b * NN + o0 + tid] = 1.0f / (1.0f + expf(-s));
    }
}

// ---------------------------------------------------------------------------
extern "C" void kernel_launch(void* const* d_in, const int* in_sizes, int n_in,
                              void* d_out, int out_size)
{
    const float* x      = (const float*)d_in[0];   // [B, N, D, S]
    const float* M      = (const float*)d_in[1];   // [N, N]
    const float* w_syn  = (const float*)d_in[2];   // [N, D, S]
    const float* b_dend = (const float*)d_in[3];   // [N, D]
    const float* w_dend = (const float*)d_in[4];   // [N, D]
    const float* b_soma = (const float*)d_in[5];   // [N]
    float* out          = (float*)d_out;           // [B, N]

    cudaFuncSetAttribute(gemm_neuron, cudaFuncAttributeMaxDynamicSharedMemorySize, SMEM_REQ);

    compress_M<<<NN / 8, 256>>>(M);
    combine_meta<<<(NN / 2) * 64 / 256, 256>>>();
    transpose_x<<<dim3(NN / 64, DS / 32, BB), 256>>>(x);
    gemm_neuron<<<dim3(NN / 128, BB), 256, SMEM_REQ>>>(
        x, w_syn, b_dend, w_dend, b_soma, out);
}

// round 7
// speedup vs baseline: 1.1802x; 1.1802x over previous
#include <cuda_runtime.h>
#include <cuda_fp16.h>
#include <math.h>
#include <stdint.h>

// Problem constants: B=64, N=1024, D=8, S=16 -> DS=128, K=1024
#define NN    1024
#define BB    64
#define DS    128
#define KDIM  1024
#define CHUNK 64                     // K per stage
#define NCH   (KDIM / CHUNK)         // 16

// smem geometry: padded-linear rows, 128B data + 16B pad = 144B stride
#define ROWB     144
#define A_BYTES  (128 * ROWB)        // 18432
#define STG_SZ   (2 * A_BYTES)       // 36864 (A then B)
#define NSTAGE   3
#define C_STRIDE 129
#define SMEM_REQ (NSTAGE * STG_SZ)   // 110592 (covers C: 128*129*4+1024=67072)

__device__ __forceinline__ uint32_t smem_u32(const void* p) {
    uint32_t a;
    asm("{ .reg .u64 t; cvta.to.shared.u64 t, %1; cvt.u32.u64 %0, t; }" : "=r"(a) : "l"(p));
    return a;
}
__device__ __forceinline__ void cp16(uint32_t dst, const void* src) {
    asm volatile("cp.async.cg.shared.global [%0], [%1], 16;" :: "r"(dst), "l"(src) : "memory");
}
__device__ __forceinline__ void ldm_x4(uint32_t* r, uint32_t addr) {
    asm volatile("ldmatrix.sync.aligned.m8n8.x4.shared.b16 {%0,%1,%2,%3}, [%4];"
                 : "=r"(r[0]), "=r"(r[1]), "=r"(r[2]), "=r"(r[3]) : "r"(addr));
}
__device__ __forceinline__ void mma16816(float* c, const uint32_t* a, uint32_t b0, uint32_t b1) {
    asm volatile("mma.sync.aligned.m16n8k16.row.col.f32.f16.f16.f32 "
                 "{%0,%1,%2,%3}, {%4,%5,%6,%7}, {%8,%9}, {%0,%1,%2,%3};"
                 : "+f"(c[0]), "+f"(c[1]), "+f"(c[2]), "+f"(c[3])
                 : "r"(a[0]), "r"(a[1]), "r"(a[2]), "r"(a[3]), "r"(b0), "r"(b1));
}

// ---------------- device scratch ------------------------------------------
__device__ __half g_A[NN * KDIM];        // M fp16, [o, i]            (2 MB)
__device__ __half g_X[BB * DS * KDIM];   // xT fp16, [(b*128+ds), i] (16 MB)

// ---------------- fused prep: M -> fp16  +  transpose x -> g_X fp16 --------
// Grid (16, 4, 64) = 4096 blocks x 256 threads.
// Each block also converts its 256-element slice of M (4096*256 = NN*NN).
__global__ void prep(const float* __restrict__ x, const float* __restrict__ M)
{
    const int tid = threadIdx.x;
    const int bid = blockIdx.x + 16 * (blockIdx.y + 4 * blockIdx.z);
    const int gid = bid * 256 + tid;
    g_A[gid] = __float2half_rn(M[gid]);

    __shared__ float t[64 * 33];
    const int b  = blockIdx.z;
    const int i0 = blockIdx.x * 64;
    const int d0 = blockIdx.y * 32;

    const float* src = x + (size_t)b * (NN * DS) + (size_t)i0 * DS + d0;
#pragma unroll
    for (int idx = tid; idx < 64 * 32; idx += 256) {
        const int r = idx >> 5, c = idx & 31;
        t[r * 33 + c] = src[(size_t)r * DS + c];
    }
    __syncthreads();

    __half2* dst = (__half2*)g_X + (size_t)(b * DS + d0) * (KDIM / 2) + (i0 >> 1);
#pragma unroll
    for (int idx = tid; idx < 32 * 32; idx += 256) {
        const int dsr = idx >> 5, hc = idx & 31;
        dst[(size_t)dsr * (KDIM / 2) + hc] =
            __floats2half2_rn(t[(2 * hc) * 33 + dsr], t[(2 * hc + 1) * 33 + dsr]);
    }
}

// ---------------- GEMM (128o x 128ds, per batch) + fused epilogue ----------
// Grid (8, 64). Block 256 = 8 warps, warp tile m64 x n32 (2 m x 4 n).
// 3-stage cp.async pipeline, ONE __syncthreads per chunk.
__global__ void __launch_bounds__(256, 2) gemm_neuron(
    const float* __restrict__ w_syn,    // [N, 128]
    const float* __restrict__ b_dend,   // [N, 8]
    const float* __restrict__ w_dend,   // [N, 8]
    const float* __restrict__ b_soma,   // [N]
    float* __restrict__ out)            // [B, N]
{
    extern __shared__ char smem[];
    const uint32_t sb = smem_u32(smem);
    const int tid  = threadIdx.x;
    const int wid  = tid >> 5, lane = tid & 31;
    const int wm   = wid & 1;           // m-warp: 64 rows
    const int wn   = wid >> 1;          // n-warp: 32 cols (0..3)
    const int o0   = blockIdx.x * 128;
    const int b    = blockIdx.y;

    // ldmatrix lane bases (linear + 16B-pad layout); add kb*32 per k16 block
    uint32_t rowA[4], rowB[2];
#pragma unroll
    for (int mt = 0; mt < 4; mt++)
        rowA[mt] = (uint32_t)(wm * 64 + mt * 16 + (lane & 15)) * ROWB + (lane >> 4) * 16;
#pragma unroll
    for (int bt = 0; bt < 2; bt++)
        rowB[bt] = A_BYTES +
            (uint32_t)(wn * 32 + bt * 16 + ((lane >> 4) & 1) * 8 + (lane & 7)) * ROWB +
            ((lane >> 3) & 1) * 16;

    float acc[4][4][4];
#pragma unroll
    for (int mt = 0; mt < 4; mt++)
#pragma unroll
        for (int nt = 0; nt < 4; nt++)
#pragma unroll
            for (int q = 0; q < 4; q++) acc[mt][nt][q] = 0.f;

    const __half* gA = g_A + (size_t)o0 * KDIM;
    const __half* gB = g_X + (size_t)(b * DS) * KDIM;

    // Stage chunk c into buffer c%3: 8 cp16 per thread (A + B)
#define STAGE(c) do {                                                           \
    const uint32_t _base = sb + ((c) % 3) * STG_SZ;                             \
    _Pragma("unroll")                                                           \
    for (int j = 0; j < 4; j++) {                                               \
        const int g   = tid + j * 256;                                          \
        const int row = g >> 3, col = g & 7;                                    \
        const uint32_t d = (uint32_t)(row * ROWB + col * 16);                   \
        cp16(_base + d,           gA + (size_t)row * KDIM + (c) * CHUNK + col * 8); \
        cp16(_base + A_BYTES + d, gB + (size_t)row * KDIM + (c) * CHUNK + col * 8); \
    }                                                                           \
    asm volatile("cp.async.commit_group;" ::: "memory");                        \
} while (0)

    STAGE(0); STAGE(1);

    for (int c = 0; c < NCH; c++) {
        // buffer c ready when group c complete
        if (c < NCH - 1) asm volatile("cp.async.wait_group 1;" ::: "memory");
        else             asm volatile("cp.async.wait_group 0;" ::: "memory");
        __syncthreads();   // also: all warps done reading buffer (c-1)%3
        if (c + 2 < NCH) STAGE(c + 2);   // writes buffer (c+2)%3 == (c-1)%3

        const uint32_t base = sb + (c % 3) * STG_SZ;
#pragma unroll
        for (int kb = 0; kb < 4; kb++) {
            uint32_t a[4][4], bf[2][4];
#pragma unroll
            for (int mt = 0; mt < 4; mt++) ldm_x4(a[mt], base + rowA[mt] + kb * 32);
#pragma unroll
            for (int bt = 0; bt < 2; bt++) ldm_x4(bf[bt], base + rowB[bt] + kb * 32);
#pragma unroll
            for (int mt = 0; mt < 4; mt++)
#pragma unroll
                for (int nt = 0; nt < 4; nt++)
                    mma16816(acc[mt][nt], a[mt],
                             bf[nt >> 1][(nt & 1) * 2], bf[nt >> 1][(nt & 1) * 2 + 1]);
        }
    }
    __syncthreads();   // all reads done before C overlays stage buffers

    // ---- epilogue: frags -> C[128][129] fp32, then fused neuron math ----
    float* C = (float*)smem;
#pragma unroll
    for (int mt = 0; mt < 4; mt++)
#pragma unroll
        for (int nt = 0; nt < 4; nt++) {
            const int r  = wm * 64 + mt * 16 + (lane >> 2);
            const int cc = wn * 32 + nt * 8 + (lane & 3) * 2;
            C[r * C_STRIDE + cc]           = acc[mt][nt][0];
            C[r * C_STRIDE + cc + 1]       = acc[mt][nt][1];
            C[(r + 8) * C_STRIDE + cc]     = acc[mt][nt][2];
            C[(r + 8) * C_STRIDE + cc + 1] = acc[mt][nt][3];
        }
    __syncthreads();

    // 2 threads per o-row: (row, half h of ds)
    const int row = tid & 127;
    const int h   = tid >> 7;
    const int o   = o0 + row;
    float td[4] = {0.f, 0.f, 0.f, 0.f};
    const float4* w4 = (const float4*)(w_syn + (size_t)o * 128 + h * 64);
#pragma unroll
    for (int j4 = 0; j4 < 16; j4++) {
        const float4 w = w4[j4];
        const int e = h * 64 + j4 * 4;
        td[j4 >> 2] += C[row * C_STRIDE + e]     * w.x
                     + C[row * C_STRIDE + e + 1] * w.y
                     + C[row * C_STRIDE + e + 2] * w.z
                     + C[row * C_STRIDE + e + 3] * w.w;
    }
    float sh = 0.f;
#pragma unroll
    for (int d = 0; d < 4; d++) {
        const int dd = h * 4 + d;
        sh += tanhf(td[d] + b_dend[o * 8 + dd]) * w_dend[o * 8 + dd];
    }
    float* spart = (float*)(smem + 128 * C_STRIDE * 4);
    spart[h * 128 + row] = sh;
    __syncthreads();
    if (tid < 128) {
        const float s = spart[tid] + spart[128 + tid] + b_soma[o0 + tid];
        out[b * NN + o0 + tid] = 1.0f / (1.0f + expf(-s));
    }
}

// ---------------------------------------------------------------------------
extern "C" void kernel_launch(void* const* d_in, const int* in_sizes, int n_in,
                              void* d_out, int out_size)
{
    const float* x      = (const float*)d_in[0];   // [B, N, D, S]
    const float* M      = (const float*)d_in[1];   // [N, N]
    const float* w_syn  = (const float*)d_in[2];   // [N, D, S]
    const float* b_dend = (const float*)d_in[3];   // [N, D]
    const float* w_dend = (const float*)d_in[4];   // [N, D]
    const float* b_soma = (const float*)d_in[5];   // [N]
    float* out          = (float*)d_out;           // [B, N]

    cudaFuncSetAttribute(gemm_neuron, cudaFuncAttributeMaxDynamicSharedMemorySize, SMEM_REQ);

    prep<<<dim3(NN / 64, DS / 32, BB), 256>>>(x, M);
    gemm_neuron<<<dim3(NN / 128, BB), 256, SMEM_REQ>>>(w_syn, b_dend, w_dend, b_soma, out);
}

// round 9
// speedup vs baseline: 1.2105x; 1.0257x over previous
#include <cuda_runtime.h>
#include <cuda_fp16.h>
#include <math.h>
#include <stdint.h>

// Problem constants: B=64, N=1024, D=8, S=16 -> DS=128, K=1024
#define NN    1024
#define BB    64
#define DS    128
#define KDIM  1024
#define CHUNK 64                     // K per stage
#define NCH   (KDIM / CHUNK)         // 16

// CTA tile: 128 o-rows x 64 ds-cols (one ds half), one batch
// smem: padded-linear rows, 128B data + 16B pad = 144B stride
#define ROWB     144
#define A_BYTES  (128 * ROWB)        // 18432
#define B_BYTES  (64 * ROWB)         // 9216
#define STG_SZ   (A_BYTES + B_BYTES) // 27648
#define C_STRIDE 68                  // epilogue fp32 row stride (64 + pad)
#define SMEM_REQ (2 * STG_SZ)        // 55296 (covers C: 128*68*4=34816 + 1KB)

__device__ __forceinline__ uint32_t smem_u32(const void* p) {
    uint32_t a;
    asm("{ .reg .u64 t; cvta.to.shared.u64 t, %1; cvt.u32.u64 %0, t; }" : "=r"(a) : "l"(p));
    return a;
}
__device__ __forceinline__ void cp16(uint32_t dst, const void* src) {
    asm volatile("cp.async.cg.shared.global [%0], [%1], 16;" :: "r"(dst), "l"(src) : "memory");
}
__device__ __forceinline__ void ldm_x4(uint32_t* r, uint32_t addr) {
    asm volatile("ldmatrix.sync.aligned.m8n8.x4.shared.b16 {%0,%1,%2,%3}, [%4];"
                 : "=r"(r[0]), "=r"(r[1]), "=r"(r[2]), "=r"(r[3]) : "r"(addr));
}
__device__ __forceinline__ void mma16816(float* c, const uint32_t* a, uint32_t b0, uint32_t b1) {
    asm volatile("mma.sync.aligned.m16n8k16.row.col.f32.f16.f16.f32 "
                 "{%0,%1,%2,%3}, {%4,%5,%6,%7}, {%8,%9}, {%0,%1,%2,%3};"
                 : "+f"(c[0]), "+f"(c[1]), "+f"(c[2]), "+f"(c[3])
                 : "r"(a[0]), "r"(a[1]), "r"(a[2]), "r"(a[3]), "r"(b0), "r"(b1));
}

// ---------------- device scratch ------------------------------------------
__device__ __half g_A[NN * KDIM];        // M fp16, [o, i]            (2 MB)
__device__ __half g_X[BB * DS * KDIM];   // xT fp16, [(b*128+ds), i] (16 MB)
__device__ float  g_partial[BB * NN];    // soma partials (2 atomic adds each)

// ---------------- fused prep: M->fp16, transpose x, zero partials ----------
// Grid (16, 4, 64) = 4096 blocks x 256 threads.
__global__ void prep(const float* __restrict__ x, const float* __restrict__ M)
{
    const int tid = threadIdx.x;
    const int bid = blockIdx.x + 16 * (blockIdx.y + 4 * blockIdx.z);
    const int gid = bid * 256 + tid;
    g_A[gid] = __float2half_rn(M[gid]);
    if (bid < (BB * NN) / 256) g_partial[gid] = 0.f;

    __shared__ float t[64 * 33];
    const int b  = blockIdx.z;
    const int i0 = blockIdx.x * 64;
    const int d0 = blockIdx.y * 32;

    const float* src = x + (size_t)b * (NN * DS) + (size_t)i0 * DS + d0;
#pragma unroll
    for (int idx = tid; idx < 64 * 32; idx += 256) {
        const int r = idx >> 5, c = idx & 31;
        t[r * 33 + c] = src[(size_t)r * DS + c];
    }
    __syncthreads();

    __half2* dst = (__half2*)g_X + (size_t)(b * DS + d0) * (KDIM / 2) + (i0 >> 1);
#pragma unroll
    for (int idx = tid; idx < 32 * 32; idx += 256) {
        const int dsr = idx >> 5, hc = idx & 31;
        dst[(size_t)dsr * (KDIM / 2) + hc] =
            __floats2half2_rn(t[(2 * hc) * 33 + dsr], t[(2 * hc + 1) * 33 + dsr]);
    }
}

// ---------------- GEMM (128o x 64ds half) + partial dendrite epilogue ------
// Grid (8, 2, 64). Block 256 = 8 warps: 4 m-warps x 2 n-warps, warp m32n32.
// 2-stage cp.async pipeline (R3-proven structure). 3 CTAs/SM target.
__global__ void __launch_bounds__(256, 3) gemm_neuron(
    const float* __restrict__ w_syn,    // [N, 128]
    const float* __restrict__ b_dend,   // [N, 8]
    const float* __restrict__ w_dend)   // [N, 8]
{
    extern __shared__ char smem[];
    const uint32_t sb = smem_u32(smem);
    const int tid  = threadIdx.x;
    const int wid  = tid >> 5, lane = tid & 31;
    const int wm   = wid & 3;           // m-warp: 32 rows
    const int wn   = wid >> 2;          // n-warp: 32 cols (0..1)
    const int o0   = blockIdx.x * 128;
    const int h    = blockIdx.y;        // ds half
    const int b    = blockIdx.z;

    // ldmatrix lane bases (linear + 16B-pad layout); add kb*32 per k16 block
    uint32_t rowA[2], rowB[2];
#pragma unroll
    for (int mt = 0; mt < 2; mt++)
        rowA[mt] = (uint32_t)(wm * 32 + mt * 16 + (lane & 15)) * ROWB + (lane >> 4) * 16;
#pragma unroll
    for (int bt = 0; bt < 2; bt++)
        rowB[bt] = A_BYTES +
            (uint32_t)(wn * 32 + bt * 16 + ((lane >> 4) & 1) * 8 + (lane & 7)) * ROWB +
            ((lane >> 3) & 1) * 16;

    float acc[2][4][4];
#pragma unroll
    for (int mt = 0; mt < 2; mt++)
#pragma unroll
        for (int nt = 0; nt < 4; nt++)
#pragma unroll
            for (int q = 0; q < 4; q++) acc[mt][nt][q] = 0.f;

    const __half* gA = g_A + (size_t)o0 * KDIM;
    const __half* gB = g_X + (size_t)(b * DS + h * 64) * KDIM;

    // Stage chunk c into buffer c&1: A 4 cp16/thread, B 2 cp16/thread
#define STAGE(c) do {                                                           \
    const uint32_t _base = sb + ((c) & 1) * STG_SZ;                             \
    _Pragma("unroll")                                                           \
    for (int j = 0; j < 4; j++) {                                               \
        const int g   = tid + j * 256;                                          \
        const int row = g >> 3, col = g & 7;                                    \
        cp16(_base + (uint32_t)(row * ROWB + col * 16),                         \
             gA + (size_t)row * KDIM + (c) * CHUNK + col * 8);                  \
    }                                                                           \
    _Pragma("unroll")                                                           \
    for (int j = 0; j < 2; j++) {                                               \
        const int g   = tid + j * 256;                                          \
        const int row = g >> 3, col = g & 7;                                    \
        cp16(_base + A_BYTES + (uint32_t)(row * ROWB + col * 16),               \
             gB + (size_t)row * KDIM + (c) * CHUNK + col * 8);                  \
    }                                                                           \
    asm volatile("cp.async.commit_group;" ::: "memory");                        \
} while (0)

    STAGE(0);
    for (int c = 0; c < NCH; c++) {
        if (c + 1 < NCH) {
            STAGE(c + 1);
            asm volatile("cp.async.wait_group 1;" ::: "memory");
        } else {
            asm volatile("cp.async.wait_group 0;" ::: "memory");
        }
        __syncthreads();

        const uint32_t base = sb + (c & 1) * STG_SZ;
#pragma unroll
        for (int kb = 0; kb < 4; kb++) {
            uint32_t a[2][4], bf[2][4];
#pragma unroll
            for (int mt = 0; mt < 2; mt++) ldm_x4(a[mt], base + rowA[mt] + kb * 32);
#pragma unroll
            for (int bt = 0; bt < 2; bt++) ldm_x4(bf[bt], base + rowB[bt] + kb * 32);
#pragma unroll
            for (int mt = 0; mt < 2; mt++)
#pragma unroll
                for (int nt = 0; nt < 4; nt++)
                    mma16816(acc[mt][nt], a[mt],
                             bf[nt >> 1][(nt & 1) * 2], bf[nt >> 1][(nt & 1) * 2 + 1]);
        }
        __syncthreads();   // all warps done reading before restage
    }

    // ---- epilogue: frags -> C[128][68] fp32 ----
    float* C = (float*)smem;
#pragma unroll
    for (int mt = 0; mt < 2; mt++)
#pragma unroll
        for (int nt = 0; nt < 4; nt++) {
            const int r  = wm * 32 + mt * 16 + (lane >> 2);
            const int cc = wn * 32 + nt * 8 + (lane & 3) * 2;
            C[r * C_STRIDE + cc]           = acc[mt][nt][0];
            C[r * C_STRIDE + cc + 1]       = acc[mt][nt][1];
            C[(r + 8) * C_STRIDE + cc]     = acc[mt][nt][2];
            C[(r + 8) * C_STRIDE + cc + 1] = acc[mt][nt][3];
        }
    __syncthreads();

    // 2 threads per o-row: quarter q covers local ds [q*32, q*32+32)
    // -> global dendrites h*4 + q*2 + {0,1}, fully local (ds = d*16 + s)
    const int row = tid & 127;
    const int q   = tid >> 7;
    const int o   = o0 + row;
    float td[2] = {0.f, 0.f};
    const float4* w4 = (const float4*)(w_syn + (size_t)o * 128 + h * 64 + q * 32);
#pragma unroll
    for (int j4 = 0; j4 < 8; j4++) {
        const float4 w = w4[j4];
        const int e = q * 32 + j4 * 4;
        td[j4 >> 2] += C[row * C_STRIDE + e]     * w.x
                     + C[row * C_STRIDE + e + 1] * w.y
                     + C[row * C_STRIDE + e + 2] * w.z
                     + C[row * C_STRIDE + e + 3] * w.w;
    }
    float sh = 0.f;
#pragma unroll
    for (int d = 0; d < 2; d++) {
        const int dd = h * 4 + q * 2 + d;
        sh += tanhf(td[d] + b_dend[o * 8 + dd]) * w_dend[o * 8 + dd];
    }
    float* spart = (float*)(smem + 128 * C_STRIDE * 4);
    spart[q * 128 + row] = sh;
    __syncthreads();
    if (tid < 128)   // one atomic per (b, o) per CTA; 2 CTAs combine (h=0,1)
        atomicAdd(&g_partial[b * NN + o0 + tid], spart[tid] + spart[128 + tid]);
}

// ---------------- finalize: sigmoid(partial + b_soma) ----------------------
__global__ void finalize(const float* __restrict__ b_soma, float* __restrict__ out)
{
    const int i = blockIdx.x * 256 + threadIdx.x;      // 0..65535
    const float s = g_partial[i] + b_soma[i & (NN - 1)];
    out[i] = 1.0f / (1.0f + expf(-s));
}

// ---------------------------------------------------------------------------
extern "C" void kernel_launch(void* const* d_in, const int* in_sizes, int n_in,
                              void* d_out, int out_size)
{
    const float* x      = (const float*)d_in[0];   // [B, N, D, S]
    const float* M      = (const float*)d_in[1];   // [N, N]
    const float* w_syn  = (const float*)d_in[2];   // [N, D, S]
    const float* b_dend = (const float*)d_in[3];   // [N, D]
    const float* w_dend = (const float*)d_in[4];   // [N, D]
    const float* b_soma = (const float*)d_in[5];   // [N]
    float* out          = (float*)d_out;           // [B, N]

    cudaFuncSetAttribute(gemm_neuron, cudaFuncAttributeMaxDynamicSharedMemorySize, SMEM_REQ);

    prep<<<dim3(NN / 64, DS / 32, BB), 256>>>(x, M);
    gemm_neuron<<<dim3(NN / 128, 2, BB), 256, SMEM_REQ>>>(w_syn, b_dend, w_dend);
    finalize<<<(BB * NN) / 256, 256>>>(b_soma, out);
}

// round 10
// speedup vs baseline: 1.4043x; 1.1601x over previous
#include <cuda_runtime.h>
#include <cuda_fp16.h>
#include <math.h>
#include <stdint.h>

// Problem constants: B=64, N=1024, D=8, S=16 -> DS=128, K=1024
#define NN    1024
#define BB    64
#define DS    128
#define KDIM  1024
#define NKB   (KDIM / 16)            // 64 k16-blocks
#define C_STRIDE 129
#define SMEM_REQ (128 * C_STRIDE * 4 + 1024)   // 67072 (epilogue only)

__device__ __forceinline__ void mma16816(float* c, const uint32_t* a, uint32_t b0, uint32_t b1) {
    asm volatile("mma.sync.aligned.m16n8k16.row.col.f32.f16.f16.f32 "
                 "{%0,%1,%2,%3}, {%4,%5,%6,%7}, {%8,%9}, {%0,%1,%2,%3};"
                 : "+f"(c[0]), "+f"(c[1]), "+f"(c[2]), "+f"(c[3])
                 : "r"(a[0]), "r"(a[1]), "r"(a[2]), "r"(a[3]), "r"(b0), "r"(b1));
}

// ---------------- device scratch: FRAGMENT-ORDERED operands ----------------
// A frags: [row16 0..63][kb 0..63][lane 0..31][4 u32]   (2 MB)
// B frags: [b*8 + n16][kb][lane][4 u32]                (16 MB)
__device__ uint32_t g_Af[64 * NKB * 128];
__device__ uint32_t g_Xf[BB * 8 * NKB * 128];

// ---------------- prep: build fragment-ordered A and B ---------------------
// Grid (64, 64): x = kb, y = row16 (A task) and y = b (B task). 256 threads.
__global__ void prep(const float* __restrict__ x, const float* __restrict__ M)
{
    const int tid = threadIdx.x;
    const int kb  = blockIdx.x;

    // ---- A task: M tile (row16, kb), 128 u32, threads 0..127 ----
    // u32 t: lane = t>>2, reg = t&3
    //   R = row16*16 + (lane>>2) + (reg&1)*8
    //   C = kb*16 + (lane&3)*2 + ((reg>>1)&1)*8 ; halves (R,C),(R,C+1)
    if (tid < 128) {
        const int row16 = blockIdx.y;
        const int lane = tid >> 2, reg = tid & 3;
        const int R = row16 * 16 + (lane >> 2) + (reg & 1) * 8;
        const int C = kb * 16 + (lane & 3) * 2 + ((reg >> 1) & 1) * 8;
        const float2 mv = *(const float2*)&M[(size_t)R * NN + C];
        const __half2 h = __floats2half2_rn(mv.x, mv.y);
        g_Af[((size_t)row16 * NKB + kb) * 128 + tid] = *(const uint32_t*)&h;
    }

    // ---- B task: x slab [b, i=kb*16..+16, ds 0..127] -> 8 n16 frag tiles ----
    __shared__ float sx[16 * 132];
    const int b = blockIdx.y;
    const float* src = x + ((size_t)b * NN + kb * 16) * DS;
#pragma unroll
    for (int j = tid; j < 16 * 128; j += 256) {
        const int r = j >> 7, c = j & 127;
        sx[r * 132 + c] = src[r * DS + c];
    }
    __syncthreads();

    // frag value: b-reg layout (k along halves):
    //   n  = n16*16 + (lane>>2) + ((reg>>1)&1)*8
    //   k0 = (lane&3)*2 + (reg&1)*8 ; halves (k0,n),(k0+1,n)
    uint32_t* dstB = g_Xf + ((size_t)(b * 8) * NKB + kb) * 128;
#pragma unroll
    for (int it = 0; it < 4; it++) {
        const int u = it * 256 + tid;          // 0..1023
        const int n16 = u >> 7, tt = u & 127;
        const int lane = tt >> 2, reg = tt & 3;
        const int n  = n16 * 16 + (lane >> 2) + ((reg >> 1) & 1) * 8;
        const int k0 = (lane & 3) * 2 + (reg & 1) * 8;
        const __half2 h = __floats2half2_rn(sx[k0 * 132 + n], sx[(k0 + 1) * 132 + n]);
        dstB[(size_t)n16 * (NKB * 128) + tt] = *(const uint32_t*)&h;
    }
}

// ---------------- GEMM: pure LDG+HMMA mainloop, no smem/barriers -----------
// Grid (8, 64): 128-o tile x batch. Block 256 = 8 warps (2 m x 4 n), m64n32.
__global__ void __launch_bounds__(256, 2) gemm_neuron(
    const float* __restrict__ w_syn,    // [N, 128]
    const float* __restrict__ b_dend,   // [N, 8]
    const float* __restrict__ w_dend,   // [N, 8]
    const float* __restrict__ b_soma,   // [N]
    float* __restrict__ out)            // [B, N]
{
    extern __shared__ char smem[];
    const int tid  = threadIdx.x;
    const int wid  = tid >> 5, lane = tid & 31;
    const int wm   = wid & 1;           // m-warp: 64 rows
    const int wn   = wid >> 1;          // n-warp: 32 cols (2 n16 tiles)
    const int o0   = blockIdx.x * 128;
    const int b    = blockIdx.y;

    const uint4* pa = (const uint4*)g_Af
                    + ((size_t)(blockIdx.x * 8 + wm * 4) * NKB) * 32 + lane;
    const uint4* pb = (const uint4*)g_Xf
                    + ((size_t)(b * 8 + wn * 2) * NKB) * 32 + lane;
    // strides (uint4 units): mt/bt tile = NKB*32 = 2048, kb step = 32

    float acc[4][4][4];
#pragma unroll
    for (int mt = 0; mt < 4; mt++)
#pragma unroll
        for (int nt = 0; nt < 4; nt++)
#pragma unroll
            for (int q = 0; q < 4; q++) acc[mt][nt][q] = 0.f;

    uint4 A0[4], B0[2], A1[4], B1[2];

#define LDFR(Ar, Br, kb) do {                                              \
    _Pragma("unroll")                                                      \
    for (int mt = 0; mt < 4; mt++) Ar[mt] = pa[mt * 2048 + (kb) * 32];     \
    _Pragma("unroll")                                                      \
    for (int bt = 0; bt < 2; bt++) Br[bt] = pb[bt * 2048 + (kb) * 32];     \
} while (0)

#define DOMMA(Ar, Br) do {                                                 \
    _Pragma("unroll")                                                      \
    for (int mt = 0; mt < 4; mt++) {                                       \
        _Pragma("unroll")                                                  \
        for (int bt = 0; bt < 2; bt++) {                                   \
            mma16816(acc[mt][bt * 2],     (const uint32_t*)&Ar[mt],        \
                     Br[bt].x, Br[bt].y);                                  \
            mma16816(acc[mt][bt * 2 + 1], (const uint32_t*)&Ar[mt],        \
                     Br[bt].z, Br[bt].w);                                  \
        }                                                                  \
    }                                                                      \
} while (0)

    LDFR(A0, B0, 0);
#pragma unroll 4
    for (int kb = 0; kb < NKB; kb += 2) {
        LDFR(A1, B1, (kb + 1) & (NKB - 1));
        DOMMA(A0, B0);
        LDFR(A0, B0, (kb + 2) & (NKB - 1));   // last iter: harmless reload of 0
        DOMMA(A1, B1);
    }

    // ---- epilogue: frags -> C[128][129] fp32, then fused neuron math ----
    float* C = (float*)smem;
#pragma unroll
    for (int mt = 0; mt < 4; mt++)
#pragma unroll
        for (int nt = 0; nt < 4; nt++) {
            const int r  = wm * 64 + mt * 16 + (lane >> 2);
            const int cc = wn * 32 + nt * 8 + (lane & 3) * 2;
            C[r * C_STRIDE + cc]           = acc[mt][nt][0];
            C[r * C_STRIDE + cc + 1]       = acc[mt][nt][1];
            C[(r + 8) * C_STRIDE + cc]     = acc[mt][nt][2];
            C[(r + 8) * C_STRIDE + cc + 1] = acc[mt][nt][3];
        }
    __syncthreads();

    // 2 threads per o-row: (row, half h of ds)
    const int row = tid & 127;
    const int h   = tid >> 7;
    const int o   = o0 + row;
    float td[4] = {0.f, 0.f, 0.f, 0.f};
    const float4* w4 = (const float4*)(w_syn + (size_t)o * 128 + h * 64);
#pragma unroll
    for (int j4 = 0; j4 < 16; j4++) {
        const float4 w = w4[j4];
        const int e = h * 64 + j4 * 4;
        td[j4 >> 2] += C[row * C_STRIDE + e]     * w.x
                     + C[row * C_STRIDE + e + 1] * w.y
                     + C[row * C_STRIDE + e + 2] * w.z
                     + C[row * C_STRIDE + e + 3] * w.w;
    }
    float sh = 0.f;
#pragma unroll
    for (int d = 0; d < 4; d++) {
        const int dd = h * 4 + d;
        sh += tanhf(td[d] + b_dend[o * 8 + dd]) * w_dend[o * 8 + dd];
    }
    float* spart = (float*)(smem + 128 * C_STRIDE * 4);
    spart[h * 128 + row] = sh;
    __syncthreads();
    if (tid < 128) {
        const float s = spart[tid] + spart[128 + tid] + b_soma[o0 + tid];
        out[b * NN + o0 + tid] = 1.0f / (1.0f + expf(-s));
    }
}

// ---------------------------------------------------------------------------
extern "C" void kernel_launch(void* const* d_in, const int* in_sizes, int n_in,
                              void* d_out, int out_size)
{
    const float* x      = (const float*)d_in[0];   // [B, N, D, S]
    const float* M      = (const float*)d_in[1];   // [N, N]
    const float* w_syn  = (const float*)d_in[2];   // [N, D, S]
    const float* b_dend = (const float*)d_in[3];   // [N, D]
    const float* w_dend = (const float*)d_in[4];   // [N, D]
    const float* b_soma = (const float*)d_in[5];   // [N]
    float* out          = (float*)d_out;           // [B, N]

    cudaFuncSetAttribute(gemm_neuron, cudaFuncAttributeMaxDynamicSharedMemorySize, SMEM_REQ);

    prep<<<dim3(64, 64), 256>>>(x, M);
    gemm_neuron<<<dim3(NN / 128, BB), 256, SMEM_REQ>>>(w_syn, b_dend, w_dend, b_soma, out);
}